// round 14
// baseline (speedup 1.0000x reference)
#include <cuda_runtime.h>
#include <cuda_bf16.h>
#include <cstdint>

// ---------------------------------------------------------------------------
// T2FN on GB300 — hi/lo bf16 planes, ldmatrix fragments, W1 pre-conversion
// hidden inside stage 1:
//  Stage 1 (k_build_F): per-b persistent CTA HMMA GEMM AV@X -> F planes,
//                       PLUS interleaved W1 fp32 -> bf16-plane conversion
//  Stage 2 (k_gemm_mma): h1_pre = F @ W1planes, split-K, pure cp.async staging
//  Stage 3 (k_finish):   reduce partials + MLP tail
// ---------------------------------------------------------------------------

#define B_    128
#define T_    64
#define ADIM  48
#define XDIM  96
#define PF    128
#define NIJ   2401        // 49*49
#define KX    97          // X+1
#define KXP   98
#define KPC   32          // pairs per chunk (64 flat k)
#define NCHUNK2 3677
#define NFLATK  235328u   // NCHUNK2*64 padded flat k rows
#define FROWP 117664u     // padded pairs per b (3677*32)
#define NSPLIT 296
#define WSTR  68          // W1 plane row stride (words)

__device__ uint32_t g_Fhi[(size_t)B_ * FROWP];
__device__ uint32_t g_Flo[(size_t)B_ * FROWP];
__device__ uint32_t g_W1hi[(size_t)NFLATK * WSTR];   // zero-init: pad rows stay 0
__device__ uint32_t g_W1lo[(size_t)NFLATK * WSTR];
__device__ float    g_part[(size_t)NSPLIT * B_ * PF];

static __device__ __forceinline__ uint32_t cvthi(float v0, float v1) {
    uint32_t h;
    asm("cvt.rn.bf16x2.f32 %0, %1, %2;" : "=r"(h) : "f"(v1), "f"(v0));
    return h;
}
static __device__ __forceinline__ void cvt2(float v0, float v1, uint32_t& h, uint32_t& l) {
    uint32_t hh = cvthi(v0, v1);
    float h0 = __uint_as_float(hh << 16);
    float h1 = __uint_as_float(hh & 0xFFFF0000u);
    float r0 = v0 - h0, r1 = v1 - h1;
    asm("cvt.rn.bf16x2.f32 %0, %1, %2;" : "=r"(l) : "f"(r1), "f"(r0));
    h = hh;
}
static __device__ __forceinline__ uint32_t smem_u32(const void* p) {
    uint32_t a;
    asm("{ .reg .u64 t; cvta.to.shared.u64 t, %1; cvt.u32.u64 %0, t; }" : "=r"(a) : "l"(p));
    return a;
}
#define CPA16(dst, src) \
    asm volatile("cp.async.cg.shared.global [%0], [%1], 16;" :: "r"(dst), "l"(src))

static __device__ __forceinline__ void mma_bf16(float* d, const uint32_t* a,
                                                const uint32_t* b) {
    asm volatile(
        "mma.sync.aligned.m16n8k16.row.col.f32.bf16.bf16.f32 "
        "{%0,%1,%2,%3}, {%4,%5,%6,%7}, {%8,%9}, {%0,%1,%2,%3};"
        : "+f"(d[0]), "+f"(d[1]), "+f"(d[2]), "+f"(d[3])
        : "r"(a[0]), "r"(a[1]), "r"(a[2]), "r"(a[3]), "r"(b[0]), "r"(b[1]));
}
static __device__ __forceinline__ void ldsm4(uint32_t* r, uint32_t addr) {
    asm volatile("ldmatrix.sync.aligned.m8n8.x4.shared.b16 {%0,%1,%2,%3}, [%4];"
                 : "=r"(r[0]), "=r"(r[1]), "=r"(r[2]), "=r"(r[3]) : "r"(addr));
}
static __device__ __forceinline__ void ldsm4t(uint32_t* r, uint32_t addr) {
    asm volatile("ldmatrix.sync.aligned.m8n8.x4.trans.shared.b16 {%0,%1,%2,%3}, [%4];"
                 : "=r"(r[0]), "=r"(r[1]), "=r"(r[2]), "=r"(r[3]) : "r"(addr));
}

static constexpr int PSTR = 36;   // A-plane row stride (u32 words)
static constexpr int XSTR = 68;   // B-plane row stride (u32 words)

// ---------------------------------------------------------------------------
// Stage 1 smem (words):
static constexpr int S1_ALO = 4608;                  // Ahi @0 (128*36)
static constexpr int S1_XHI = 9216;                  // Xhi [64 t][68]
static constexpr int S1_XLO = S1_XHI + 64 * XSTR;    // 13568
static constexpr int S1_AUD = S1_XLO + 64 * XSTR;    // 17920
static constexpr int S1_VID = S1_AUD + T_ * 49;      // 21056
static constexpr int S1_WORDS = S1_VID + T_ * 49;    // 24192
static constexpr int S1_BYTES = S1_WORDS * 4;        // 96768

__global__ __launch_bounds__(256, 2)
void k_build_F(const float* __restrict__ audio,
               const float* __restrict__ video,
               const float* __restrict__ text,
               const float* __restrict__ W1) {
    extern __shared__ uint32_t smw[];
    uint32_t* Ahi = smw;
    uint32_t* Alo = smw + S1_ALO;
    uint32_t* Xhi = smw + S1_XHI;
    uint32_t* Xlo = smw + S1_XLO;
    uint32_t* stg = smw;                 // epilogue overlay
    float* aud = reinterpret_cast<float*>(smw + S1_AUD);
    float* vid = reinterpret_cast<float*>(smw + S1_VID);

    const int b      = blockIdx.y;
    const int tstart = blockIdx.x ? 10 : 0;
    const int tend   = blockIdx.x ? 19 : 10;
    const int tid = threadIdx.x;
    const int wid = tid >> 5;
    const int lid = tid & 31;
    const int g   = lid >> 2;
    const int tg  = lid & 3;
    const int mbase = (wid >> 2) * 64;
    const int nbase = (wid & 3) * 32;

    // W1-convert slice for this CTA
    const uint32_t cid = (uint32_t)blockIdx.y * 2 + blockIdx.x;
    const uint32_t conv0 = cid * 920u;
    uint32_t conv_done = 0;

    // ---- one-time staging: aud/vid + X planes ([t][n] bf16) ----
#pragma unroll 3
    for (int idx = tid; idx < T_ * ADIM; idx += 256) {
        int t = idx / ADIM, c = idx - t * ADIM;
        aud[t * 49 + c] = audio[(size_t)b * (T_ * ADIM) + idx];
        vid[t * 49 + c] = video[(size_t)b * (T_ * ADIM) + idx];
    }
#pragma unroll
    for (int r = 0; r < 8; r++) {
        int t = wid * 8 + r;
        const float* trow = &text[((size_t)b * T_ + t) * XDIM];
#pragma unroll
        for (int h = 0; h < 2; h++) {
            int c  = lid + h * 32;
            int n0 = 2 * c, n1 = 2 * c + 1;
            float v0 = (n0 == 0) ? 1.f : ((n0 < KX) ? trow[n0 - 1] : 0.f);
            float v1 = (n1 < KX) ? trow[n1 - 1] : 0.f;
            uint32_t hw, lw;
            cvt2(v0, v1, hw, lw);
            Xhi[t * XSTR + c] = hw;
            Xlo[t * XSTR + c] = lw;
        }
    }
    __syncthreads();

    const uint32_t aOff = (uint32_t)(mbase + (lid & 15)) * (PSTR * 4) + (lid >> 4) * 16;
    const uint32_t aAhi = smem_u32(Ahi) + aOff;
    const uint32_t aAlo = smem_u32(Alo) + aOff;
    const uint32_t bOff = (uint32_t)(lid & 15) * (XSTR * 4) + (uint32_t)(nbase + (lid >> 4) * 8) * 2;
    const uint32_t aXhi = smem_u32(Xhi) + bOff;
    const uint32_t aXlo = smem_u32(Xlo) + bOff;

    for (int tile = tstart; tile < tend; tile++) {
        const int ij0 = tile * 128;

        // ---- AV planes [ijl][t-pair] ----
        {
            const int tp = tid & 31;
            const int r0 = tid >> 5;
            const int t0 = 2 * tp;
#pragma unroll 4
            for (int it = 0; it < 16; it++) {
                int ijl = it * 8 + r0;
                int ij  = ij0 + ijl;
                float v0 = 0.f, v1 = 0.f;
                if (ij < NIJ) {
                    int i = ij / 49;
                    int j = ij - i * 49;
                    float a0 = i ? aud[t0 * 49 + (i - 1)] : 1.f;
                    float a1 = i ? aud[(t0 + 1) * 49 + (i - 1)] : 1.f;
                    float w0 = j ? vid[t0 * 49 + (j - 1)] : 1.f;
                    float w1 = j ? vid[(t0 + 1) * 49 + (j - 1)] : 1.f;
                    v0 = a0 * w0;
                    v1 = a1 * w1;
                }
                uint32_t h, l;
                cvt2(v0, v1, h, l);
                Ahi[ijl * PSTR + tp] = h;
                Alo[ijl * PSTR + tp] = l;
            }
        }
        __syncthreads();

        // ---- 3-combo HMMA, K=64 ----
        float acc[4][4][4];
#pragma unroll
        for (int mt = 0; mt < 4; mt++)
#pragma unroll
            for (int nt = 0; nt < 4; nt++)
#pragma unroll
                for (int r = 0; r < 4; r++) acc[mt][nt][r] = 0.f;

#pragma unroll
        for (int ks = 0; ks < 4; ks++) {
            uint32_t bh[8], bl[8];
            const uint32_t bk = (uint32_t)ks * 16 * (XSTR * 4);
            ldsm4t(bh + 0, aXhi + bk);
            ldsm4t(bh + 4, aXhi + bk + 32);
            ldsm4t(bl + 0, aXlo + bk);
            ldsm4t(bl + 4, aXlo + bk + 32);
#pragma unroll
            for (int mt = 0; mt < 4; mt++) {
                const uint32_t am = (uint32_t)mt * 16 * (PSTR * 4) + (uint32_t)ks * 32;
                uint32_t ah[4], al[4];
                ldsm4(ah, aAhi + am);
                ldsm4(al, aAlo + am);
#pragma unroll
                for (int nt = 0; nt < 4; nt++) {
                    mma_bf16(acc[mt][nt], ah, &bh[2 * nt]);
                    mma_bf16(acc[mt][nt], ah, &bl[2 * nt]);
                    mma_bf16(acc[mt][nt], al, &bh[2 * nt]);
                }
            }
        }
        __syncthreads();   // fragment loads done before staging overwrite

        const int nrows = (NIJ - ij0 < 128) ? (NIJ - ij0) : 128;
        const int nw = nrows * 49;
        const size_t gbase = (size_t)b * FROWP + (size_t)ij0 * 49;

        // ---- pass 1: hi plane (single cvt2; lo stashed back into acc) ----
#pragma unroll
        for (int mt = 0; mt < 4; mt++) {
            int row = mbase + mt * 16 + g;
#pragma unroll
            for (int nt = 0; nt < 4; nt++) {
                int col = nbase + nt * 8 + 2 * tg;
                uint32_t h0, l0, h1, l1;
                cvt2(acc[mt][nt][0], acc[mt][nt][1], h0, l0);
                cvt2(acc[mt][nt][2], acc[mt][nt][3], h1, l1);
                acc[mt][nt][0] = __uint_as_float(l0);
                acc[mt][nt][1] = __uint_as_float(l1);
                if (col > 96) continue;
                int pr = col >> 1;
                stg[row * 49 + pr]       = h0;
                stg[(row + 8) * 49 + pr] = h1;
            }
        }
        __syncthreads();
        for (int idx = tid; idx < nw; idx += 256) g_Fhi[gbase + idx] = stg[idx];
        __syncthreads();

        // ---- pass 2: lo plane from stashed words ----
#pragma unroll
        for (int mt = 0; mt < 4; mt++) {
            int row = mbase + mt * 16 + g;
#pragma unroll
            for (int nt = 0; nt < 4; nt++) {
                int col = nbase + nt * 8 + 2 * tg;
                if (col > 96) continue;
                int pr = col >> 1;
                stg[row * 49 + pr]       = __float_as_uint(acc[mt][nt][0]);
                stg[(row + 8) * 49 + pr] = __float_as_uint(acc[mt][nt][1]);
            }
        }
        __syncthreads();
        for (int idx = tid; idx < nw; idx += 256) g_Flo[gbase + idx] = stg[idx];
        __syncthreads();

        // ---- interleaved W1 conversion: ~92 rows per tile ----
        {
            uint32_t c0 = conv0 + conv_done;
            uint32_t c1 = c0 + 92;
            conv_done += 92;
            for (uint32_t rr = c0 + wid; rr < c1; rr += 8) {
                if (rr >= NFLATK) break;
                uint32_t ij = rr / KXP;
                uint32_t cc = rr - ij * KXP;
                if (cc >= KX || ij >= NIJ) continue;   // pad rows stay zero-init
                const float2* src = reinterpret_cast<const float2*>(
                    W1 + ((size_t)ij * KX + cc) * PF);
                float2 w0 = src[lid];
                float2 w1 = src[lid + 32];
                uint32_t h0, l0, h1, l1;
                cvt2(w0.x, w0.y, h0, l0);
                cvt2(w1.x, w1.y, h1, l1);
                size_t ro = (size_t)rr * WSTR;
                g_W1hi[ro + lid]      = h0;
                g_W1hi[ro + lid + 32] = h1;
                g_W1lo[ro + lid]      = l0;
                g_W1lo[ro + lid + 32] = l1;
            }
        }
    }

    // ---- convert tail (CTAs with 9 tiles) ----
    {
        uint32_t c0 = conv0 + conv_done;
        uint32_t c1 = conv0 + 920u;
        for (uint32_t rr = c0 + wid; rr < c1; rr += 8) {
            if (rr >= NFLATK) break;
            uint32_t ij = rr / KXP;
            uint32_t cc = rr - ij * KXP;
            if (cc >= KX || ij >= NIJ) continue;
            const float2* src = reinterpret_cast<const float2*>(
                W1 + ((size_t)ij * KX + cc) * PF);
            float2 w0 = src[lid];
            float2 w1 = src[lid + 32];
            uint32_t h0, l0, h1, l1;
            cvt2(w0.x, w0.y, h0, l0);
            cvt2(w1.x, w1.y, h1, l1);
            size_t ro = (size_t)rr * WSTR;
            g_W1hi[ro + lid]      = h0;
            g_W1hi[ro + lid + 32] = h1;
            g_W1lo[ro + lid]      = l0;
            g_W1lo[ro + lid + 32] = l1;
        }
    }
}

// ---------------------------------------------------------------------------
// Stage 2: split-K HMMA GEMM, all-cp.async staging. grid NSPLIT, block 256.
static constexpr int S2_ALO = 4608;                  // Ahi @0
static constexpr int S2_BHI = 9216;                  // Bhi [64 k][68]
static constexpr int S2_BLO = S2_BHI + 64 * XSTR;    // 13568
static constexpr int S2_WORDS = S2_BLO + 64 * XSTR;  // 17920
static constexpr int S2_BYTES = S2_WORDS * 4;        // 71680

__global__ __launch_bounds__(256, 2)
void k_gemm_mma() {
    extern __shared__ uint32_t smw[];
    const uint32_t smb = smem_u32(smw);

    const int tid = threadIdx.x;
    const int wid = tid >> 5;
    const int lid = tid & 31;
    const int mbase = (wid >> 2) * 64;
    const int nbase = (wid & 3) * 32;
    const int g  = lid >> 2;
    const int tg = lid & 3;

    const uint32_t aOff = (uint32_t)(mbase + (lid & 15)) * (PSTR * 4) + (lid >> 4) * 16;
    const uint32_t aAhi = smb + aOff;
    const uint32_t aAlo = smb + (uint32_t)S2_ALO * 4 + aOff;
    const uint32_t bOff = (uint32_t)(lid & 15) * (XSTR * 4) + (uint32_t)(nbase + (lid >> 4) * 8) * 2;
    const uint32_t aBhi = smb + (uint32_t)S2_BHI * 4 + bOff;
    const uint32_t aBlo = smb + (uint32_t)S2_BLO * 4 + bOff;

    float acc[4][4][4];
#pragma unroll
    for (int mt = 0; mt < 4; mt++)
#pragma unroll
        for (int nt = 0; nt < 4; nt++)
#pragma unroll
            for (int r = 0; r < 4; r++) acc[mt][nt][r] = 0.f;

    for (int c = blockIdx.x; c < NCHUNK2; c += NSPLIT) {
        const uint32_t kp_base = (uint32_t)c * KPC;     // A pair offset
        const uint32_t fk_base = (uint32_t)c * 64u;     // B flat-k row offset
        __syncthreads();   // prev fragment loads done

        // ---- A: raw cp.async plane copies (128 rows x 8 uint4 x 2 planes) ----
#pragma unroll
        for (int it = 0; it < 4; it++) {
            int idx = it * 256 + tid;
            int row = idx >> 3;
            int q4  = (idx & 7) * 4;
            CPA16(smb + (uint32_t)(row * PSTR + q4) * 4,
                  &g_Fhi[(size_t)row * FROWP + kp_base + q4]);
        }
#pragma unroll
        for (int it = 0; it < 4; it++) {
            int idx = it * 256 + tid;
            int row = idx >> 3;
            int q4  = (idx & 7) * 4;
            CPA16(smb + (uint32_t)(S2_ALO + row * PSTR + q4) * 4,
                  &g_Flo[(size_t)row * FROWP + kp_base + q4]);
        }

        // ---- B: raw cp.async of W1 plane rows (64 rows x 17 uint4 x 2) ----
#pragma unroll
        for (int it = 0; it < 5; it++) {
            int idx = it * 256 + tid;
            if (idx < 1088) {
                int r = idx / 17;
                int q = idx - r * 17;
                CPA16(smb + (uint32_t)(S2_BHI + r * XSTR + q * 4) * 4,
                      &g_W1hi[(size_t)(fk_base + r) * WSTR + q * 4]);
            }
        }
#pragma unroll
        for (int it = 0; it < 5; it++) {
            int idx = it * 256 + tid;
            if (idx < 1088) {
                int r = idx / 17;
                int q = idx - r * 17;
                CPA16(smb + (uint32_t)(S2_BLO + r * XSTR + q * 4) * 4,
                      &g_W1lo[(size_t)(fk_base + r) * WSTR + q * 4]);
            }
        }
        asm volatile("cp.async.commit_group;");
        asm volatile("cp.async.wait_group 0;");
        __syncthreads();

        // ---- compute: 4 ksteps x 3 combos ----
#pragma unroll
        for (int ks = 0; ks < 4; ks++) {
            uint32_t bh[8], bl[8];
            const uint32_t bk = (uint32_t)ks * 16 * (XSTR * 4);
            ldsm4t(bh + 0, aBhi + bk);
            ldsm4t(bh + 4, aBhi + bk + 32);
            ldsm4t(bl + 0, aBlo + bk);
            ldsm4t(bl + 4, aBlo + bk + 32);
#pragma unroll
            for (int mt = 0; mt < 4; mt++) {
                const uint32_t am = (uint32_t)mt * 16 * (PSTR * 4) + (uint32_t)ks * 32;
                uint32_t ah[4], al[4];
                ldsm4(ah, aAhi + am);
                ldsm4(al, aAlo + am);
#pragma unroll
                for (int nt = 0; nt < 4; nt++) {
                    mma_bf16(acc[mt][nt], ah, &bh[2 * nt]);
                    mma_bf16(acc[mt][nt], ah, &bl[2 * nt]);
                    mma_bf16(acc[mt][nt], al, &bh[2 * nt]);
                }
            }
        }
    }

    float* part = &g_part[(size_t)blockIdx.x * (B_ * PF)];
#pragma unroll
    for (int mt = 0; mt < 4; mt++) {
        int row = mbase + mt * 16 + g;
#pragma unroll
        for (int nt = 0; nt < 4; nt++) {
            int col = nbase + nt * 8 + 2 * tg;
            *reinterpret_cast<float2*>(&part[(size_t)row * PF + col]) =
                make_float2(acc[mt][nt][0], acc[mt][nt][1]);
            *reinterpret_cast<float2*>(&part[(size_t)(row + 8) * PF + col]) =
                make_float2(acc[mt][nt][2], acc[mt][nt][3]);
        }
    }
}

// ---------------------------------------------------------------------------
__global__ void k_finish(const float* __restrict__ b1, const float* __restrict__ W2,
                         const float* __restrict__ b2, const float* __restrict__ W3,
                         const float* __restrict__ b3, float* __restrict__ out) {
    __shared__ float h1s[PF];
    __shared__ float red[PF];
    const int b = blockIdx.x;
    const int q = threadIdx.x;

    float s0 = 0.f, s1 = 0.f, s2 = 0.f, s3 = 0.f;
    const size_t off = (size_t)b * PF + q;
#pragma unroll 4
    for (int c = 0; c < NSPLIT; c += 4) {
        s0 += g_part[(size_t)(c + 0) * (B_ * PF) + off];
        s1 += g_part[(size_t)(c + 1) * (B_ * PF) + off];
        s2 += g_part[(size_t)(c + 2) * (B_ * PF) + off];
        s3 += g_part[(size_t)(c + 3) * (B_ * PF) + off];
    }
    float h1 = (s0 + s1) + (s2 + s3) + b1[q];
    h1s[q] = fmaxf(h1, 0.f);
    __syncthreads();

    float a0 = b2[q], a1 = 0.f, a2 = 0.f, a3 = 0.f;
#pragma unroll 8
    for (int p = 0; p < PF; p += 4) {
        a0 = fmaf(h1s[p + 0], W2[(p + 0) * PF + q], a0);
        a1 = fmaf(h1s[p + 1], W2[(p + 1) * PF + q], a1);
        a2 = fmaf(h1s[p + 2], W2[(p + 2) * PF + q], a2);
        a3 = fmaf(h1s[p + 3], W2[(p + 3) * PF + q], a3);
    }
    float h2 = fmaxf((a0 + a1) + (a2 + a3), 0.f);

    red[q] = h2 * W3[q];
    __syncthreads();
    for (int s = 64; s > 0; s >>= 1) {
        if (q < s) red[q] += red[q + s];
        __syncthreads();
    }
    if (q == 0) {
        float z = red[0] + b3[0];
        out[b] = 6.f / (1.f + expf(-z)) - 3.f;
    }
}

// ---------------------------------------------------------------------------
extern "C" void kernel_launch(void* const* d_in, const int* in_sizes, int n_in,
                              void* d_out, int out_size) {
    const float* audio = (const float*)d_in[0];
    const float* video = (const float*)d_in[1];
    const float* text  = (const float*)d_in[2];
    const float* W1    = (const float*)d_in[3];
    const float* b1    = (const float*)d_in[4];
    const float* W2    = (const float*)d_in[5];
    const float* b2    = (const float*)d_in[6];
    const float* W3    = (const float*)d_in[7];
    const float* b3    = (const float*)d_in[8];
    float* out = (float*)d_out;

    cudaFuncSetAttribute(k_build_F, cudaFuncAttributeMaxDynamicSharedMemorySize, S1_BYTES);
    cudaFuncSetAttribute(k_gemm_mma, cudaFuncAttributeMaxDynamicSharedMemorySize, S2_BYTES);

    k_build_F<<<dim3(2, 128), 256, S1_BYTES>>>(audio, video, text, W1);
    k_gemm_mma<<<NSPLIT, 256, S2_BYTES>>>();
    k_finish<<<128, 128>>>(b1, W2, b2, W3, b3, out);
}

// round 15
// speedup vs baseline: 1.4336x; 1.4336x over previous
#include <cuda_runtime.h>
#include <cuda_bf16.h>
#include <cstdint>

// ---------------------------------------------------------------------------
// T2FN on GB300 — hi/lo bf16 planes, ldmatrix fragments, pipelined stage 2:
//  Stage 1 (k_build_F): per-b persistent CTA HMMA GEMM AV@X -> F planes
//  Stage 2 (k_gemm_mma): h1_pre = F @ W1, split-K, double-buffered cp.async
//                        (A planes raw; W1 fp32 staged + smem-local convert)
//  Stage 3 (k_finish):   reduce partials + MLP tail
// ---------------------------------------------------------------------------

#define B_    128
#define T_    64
#define ADIM  48
#define XDIM  96
#define PF    128
#define NIJ   2401        // 49*49
#define KX    97          // X+1
#define KXP   98
#define FROWP 117664u     // padded pairs per b
#define NSPLIT 296

__device__ uint32_t g_Fhi[(size_t)B_ * FROWP];
__device__ uint32_t g_Flo[(size_t)B_ * FROWP];
__device__ float    g_part[(size_t)NSPLIT * B_ * PF];
__device__ __align__(16) float g_zero[32];          // zero-init source for pad rows

static __device__ __forceinline__ uint32_t cvthi(float v0, float v1) {
    uint32_t h;
    asm("cvt.rn.bf16x2.f32 %0, %1, %2;" : "=r"(h) : "f"(v1), "f"(v0));
    return h;
}
static __device__ __forceinline__ void cvt2(float v0, float v1, uint32_t& h, uint32_t& l) {
    uint32_t hh = cvthi(v0, v1);
    float h0 = __uint_as_float(hh << 16);
    float h1 = __uint_as_float(hh & 0xFFFF0000u);
    float r0 = v0 - h0, r1 = v1 - h1;
    asm("cvt.rn.bf16x2.f32 %0, %1, %2;" : "=r"(l) : "f"(r1), "f"(r0));
    h = hh;
}
static __device__ __forceinline__ uint32_t smem_u32(const void* p) {
    uint32_t a;
    asm("{ .reg .u64 t; cvta.to.shared.u64 t, %1; cvt.u32.u64 %0, t; }" : "=r"(a) : "l"(p));
    return a;
}
#define CPA16(dst, src) \
    asm volatile("cp.async.cg.shared.global [%0], [%1], 16;" :: "r"(dst), "l"(src))

static __device__ __forceinline__ void mma_bf16(float* d, const uint32_t* a,
                                                const uint32_t* b) {
    asm volatile(
        "mma.sync.aligned.m16n8k16.row.col.f32.bf16.bf16.f32 "
        "{%0,%1,%2,%3}, {%4,%5,%6,%7}, {%8,%9}, {%0,%1,%2,%3};"
        : "+f"(d[0]), "+f"(d[1]), "+f"(d[2]), "+f"(d[3])
        : "r"(a[0]), "r"(a[1]), "r"(a[2]), "r"(a[3]), "r"(b[0]), "r"(b[1]));
}
static __device__ __forceinline__ void ldsm4(uint32_t* r, uint32_t addr) {
    asm volatile("ldmatrix.sync.aligned.m8n8.x4.shared.b16 {%0,%1,%2,%3}, [%4];"
                 : "=r"(r[0]), "=r"(r[1]), "=r"(r[2]), "=r"(r[3]) : "r"(addr));
}
static __device__ __forceinline__ void ldsm4t(uint32_t* r, uint32_t addr) {
    asm volatile("ldmatrix.sync.aligned.m8n8.x4.trans.shared.b16 {%0,%1,%2,%3}, [%4];"
                 : "=r"(r[0]), "=r"(r[1]), "=r"(r[2]), "=r"(r[3]) : "r"(addr));
}

static constexpr int PSTR = 36;   // stage-1 A-plane row stride (u32 words)
static constexpr int XSTR = 68;   // [k][n] bf16 plane row stride (u32 words)

// ===========================================================================
// Stage 1 (R12 structure; uint4 epilogue copies, single-cvt2 pass)
static constexpr int S1_ALO = 4608;                  // Ahi @0 (128*36)
static constexpr int S1_XHI = 9216;                  // Xhi [64 t][68]
static constexpr int S1_XLO = S1_XHI + 64 * XSTR;    // 13568
static constexpr int S1_AUD = S1_XLO + 64 * XSTR;    // 17920
static constexpr int S1_VID = S1_AUD + T_ * 49;      // 21056
static constexpr int S1_WORDS = S1_VID + T_ * 49;    // 24192
static constexpr int S1_BYTES = S1_WORDS * 4;        // 96768

__global__ __launch_bounds__(256, 2)
void k_build_F(const float* __restrict__ audio,
               const float* __restrict__ video,
               const float* __restrict__ text) {
    extern __shared__ uint32_t smw[];
    uint32_t* Ahi = smw;
    uint32_t* Alo = smw + S1_ALO;
    uint32_t* Xhi = smw + S1_XHI;
    uint32_t* Xlo = smw + S1_XLO;
    uint32_t* stg = smw;                 // epilogue overlay (6272 <= 9216 words)
    float* aud = reinterpret_cast<float*>(smw + S1_AUD);
    float* vid = reinterpret_cast<float*>(smw + S1_VID);

    const int b      = blockIdx.y;
    const int tstart = blockIdx.x ? 10 : 0;
    const int tend   = blockIdx.x ? 19 : 10;
    const int tid = threadIdx.x;
    const int wid = tid >> 5;
    const int lid = tid & 31;
    const int g   = lid >> 2;
    const int tg  = lid & 3;
    const int mbase = (wid >> 2) * 64;
    const int nbase = (wid & 3) * 32;

#pragma unroll 3
    for (int idx = tid; idx < T_ * ADIM; idx += 256) {
        int t = idx / ADIM, c = idx - t * ADIM;
        aud[t * 49 + c] = audio[(size_t)b * (T_ * ADIM) + idx];
        vid[t * 49 + c] = video[(size_t)b * (T_ * ADIM) + idx];
    }
#pragma unroll
    for (int r = 0; r < 8; r++) {
        int t = wid * 8 + r;
        const float* trow = &text[((size_t)b * T_ + t) * XDIM];
#pragma unroll
        for (int h = 0; h < 2; h++) {
            int c  = lid + h * 32;
            int n0 = 2 * c, n1 = 2 * c + 1;
            float v0 = (n0 == 0) ? 1.f : ((n0 < KX) ? trow[n0 - 1] : 0.f);
            float v1 = (n1 < KX) ? trow[n1 - 1] : 0.f;
            uint32_t hw, lw;
            cvt2(v0, v1, hw, lw);
            Xhi[t * XSTR + c] = hw;
            Xlo[t * XSTR + c] = lw;
        }
    }
    __syncthreads();

    const uint32_t aOff = (uint32_t)(mbase + (lid & 15)) * (PSTR * 4) + (lid >> 4) * 16;
    const uint32_t aAhi = smem_u32(Ahi) + aOff;
    const uint32_t aAlo = smem_u32(Alo) + aOff;
    const uint32_t bOff = (uint32_t)(lid & 15) * (XSTR * 4) + (uint32_t)(nbase + (lid >> 4) * 8) * 2;
    const uint32_t aXhi = smem_u32(Xhi) + bOff;
    const uint32_t aXlo = smem_u32(Xlo) + bOff;

    for (int tile = tstart; tile < tend; tile++) {
        const int ij0 = tile * 128;

        // ---- AV planes [ijl][t-pair] ----
        {
            const int tp = tid & 31;
            const int r0 = tid >> 5;
            const int t0 = 2 * tp;
#pragma unroll 4
            for (int it = 0; it < 16; it++) {
                int ijl = it * 8 + r0;
                int ij  = ij0 + ijl;
                float v0 = 0.f, v1 = 0.f;
                if (ij < NIJ) {
                    int i = ij / 49;
                    int j = ij - i * 49;
                    float a0 = i ? aud[t0 * 49 + (i - 1)] : 1.f;
                    float a1 = i ? aud[(t0 + 1) * 49 + (i - 1)] : 1.f;
                    float w0 = j ? vid[t0 * 49 + (j - 1)] : 1.f;
                    float w1 = j ? vid[(t0 + 1) * 49 + (j - 1)] : 1.f;
                    v0 = a0 * w0;
                    v1 = a1 * w1;
                }
                uint32_t h, l;
                cvt2(v0, v1, h, l);
                Ahi[ijl * PSTR + tp] = h;
                Alo[ijl * PSTR + tp] = l;
            }
        }
        __syncthreads();

        // ---- 3-combo HMMA, K=64 ----
        float acc[4][4][4];
#pragma unroll
        for (int mt = 0; mt < 4; mt++)
#pragma unroll
            for (int nt = 0; nt < 4; nt++)
#pragma unroll
                for (int r = 0; r < 4; r++) acc[mt][nt][r] = 0.f;

#pragma unroll
        for (int ks = 0; ks < 4; ks++) {
            uint32_t bh[8], bl[8];
            const uint32_t bk = (uint32_t)ks * 16 * (XSTR * 4);
            ldsm4t(bh + 0, aXhi + bk);
            ldsm4t(bh + 4, aXhi + bk + 32);
            ldsm4t(bl + 0, aXlo + bk);
            ldsm4t(bl + 4, aXlo + bk + 32);
#pragma unroll
            for (int mt = 0; mt < 4; mt++) {
                const uint32_t am = (uint32_t)mt * 16 * (PSTR * 4) + (uint32_t)ks * 32;
                uint32_t ah[4], al[4];
                ldsm4(ah, aAhi + am);
                ldsm4(al, aAlo + am);
#pragma unroll
                for (int nt = 0; nt < 4; nt++) {
                    mma_bf16(acc[mt][nt], ah, &bh[2 * nt]);
                    mma_bf16(acc[mt][nt], ah, &bl[2 * nt]);
                    mma_bf16(acc[mt][nt], al, &bh[2 * nt]);
                }
            }
        }
        __syncthreads();   // fragment loads done before staging overwrite

        const int nrows = (NIJ - ij0 < 128) ? (NIJ - ij0) : 128;
        const int nw = nrows * 49;
        const int nq = nw >> 2;
        const size_t gbase = (size_t)b * FROWP + (size_t)ij0 * 49;

        // ---- pass 1: hi plane (single cvt2; lo stashed into acc) ----
#pragma unroll
        for (int mt = 0; mt < 4; mt++) {
            int row = mbase + mt * 16 + g;
#pragma unroll
            for (int nt = 0; nt < 4; nt++) {
                int col = nbase + nt * 8 + 2 * tg;
                uint32_t h0, l0, h1, l1;
                cvt2(acc[mt][nt][0], acc[mt][nt][1], h0, l0);
                cvt2(acc[mt][nt][2], acc[mt][nt][3], h1, l1);
                acc[mt][nt][0] = __uint_as_float(l0);
                acc[mt][nt][1] = __uint_as_float(l1);
                if (col > 96) continue;
                int pr = col >> 1;
                stg[row * 49 + pr]       = h0;
                stg[(row + 8) * 49 + pr] = h1;
            }
        }
        __syncthreads();
        {
            const uint4* s4 = reinterpret_cast<const uint4*>(stg);
            uint4* d4 = reinterpret_cast<uint4*>(g_Fhi + gbase);
            for (int idx = tid; idx < nq; idx += 256) d4[idx] = s4[idx];
            for (int idx = (nq << 2) + tid; idx < nw; idx += 256)
                g_Fhi[gbase + idx] = stg[idx];
        }
        __syncthreads();

        // ---- pass 2: lo plane from stashed words ----
#pragma unroll
        for (int mt = 0; mt < 4; mt++) {
            int row = mbase + mt * 16 + g;
#pragma unroll
            for (int nt = 0; nt < 4; nt++) {
                int col = nbase + nt * 8 + 2 * tg;
                if (col > 96) continue;
                int pr = col >> 1;
                stg[row * 49 + pr]       = __float_as_uint(acc[mt][nt][0]);
                stg[(row + 8) * 49 + pr] = __float_as_uint(acc[mt][nt][1]);
            }
        }
        __syncthreads();
        {
            const uint4* s4 = reinterpret_cast<const uint4*>(stg);
            uint4* d4 = reinterpret_cast<uint4*>(g_Flo + gbase);
            for (int idx = tid; idx < nq; idx += 256) d4[idx] = s4[idx];
            for (int idx = (nq << 2) + tid; idx < nw; idx += 256)
                g_Flo[gbase + idx] = stg[idx];
        }
        __syncthreads();
    }
}

// ===========================================================================
// Stage 2: split-K HMMA GEMM, double-buffered cp.async pipeline.
// chunk = 16 pairs (32 flat k). NCHUNK = FROWP/16 = 7354.
#define KPC2   16
#define NCHUNK 7354
static constexpr int PSTR2 = 20;   // A chunk plane row stride (16 data + 4 pad)
static constexpr int WS2   = 132;  // W1 fp32 stage row stride

// smem word offsets
static constexpr int S2_ABUF   = 0;          // 2 bufs x (Ahi 2560 + Alo 2560)
static constexpr int S2_BHI    = 10240;      // 32 x 68
static constexpr int S2_BLO    = 12416;
static constexpr int S2_WST    = 14592;      // 2 bufs x (32 x 132)
static constexpr int S2_WORDS  = 23040;
static constexpr int S2_BYTES  = S2_WORDS * 4;   // 92160

__global__ __launch_bounds__(256, 2)
void k_gemm_mma(const float* __restrict__ W1) {
    extern __shared__ uint32_t smw[];
    const uint32_t smb = smem_u32(smw);

    const int tid = threadIdx.x;
    const int wid = tid >> 5;
    const int lid = tid & 31;
    const int mbase = (wid >> 2) * 64;
    const int nbase = (wid & 3) * 32;
    const int g  = lid >> 2;
    const int tg = lid & 3;

    const uint32_t aOff = (uint32_t)(mbase + (lid & 15)) * (PSTR2 * 4) + (lid >> 4) * 16;
    const uint32_t bOff = (uint32_t)(lid & 15) * (XSTR * 4) + (uint32_t)(nbase + (lid >> 4) * 8) * 2;
    const uint32_t aBhi = smb + (uint32_t)S2_BHI * 4 + bOff;
    const uint32_t aBlo = smb + (uint32_t)S2_BLO * 4 + bOff;

    float acc[4][4][4];
#pragma unroll
    for (int mt = 0; mt < 4; mt++)
#pragma unroll
        for (int nt = 0; nt < 4; nt++)
#pragma unroll
            for (int r = 0; r < 4; r++) acc[mt][nt][r] = 0.f;

    // ---- stage helper (A raw planes + W1 fp32) via cp.async ----
    auto stage = [&](int c, int p) {
        const uint32_t kp_base = (uint32_t)c * KPC2;
        const uint32_t abase = (uint32_t)(S2_ABUF + p * 5120);
        // A: 2 planes x 128 rows x 4 uint4 = 1024 slots -> 4 iters
#pragma unroll
        for (int it = 0; it < 2; it++) {
            int idx = it * 256 + tid;
            int row = idx >> 2;
            int q4  = (idx & 3) * 4;
            CPA16(smb + (abase + row * PSTR2 + q4) * 4,
                  &g_Fhi[(size_t)row * FROWP + kp_base + q4]);
        }
#pragma unroll
        for (int it = 0; it < 2; it++) {
            int idx = it * 256 + tid;
            int row = idx >> 2;
            int q4  = (idx & 3) * 4;
            CPA16(smb + (abase + 2560 + row * PSTR2 + q4) * 4,
                  &g_Flo[(size_t)row * FROWP + kp_base + q4]);
        }
        // W1: 32 rows x 32 uint4 = 1024 slots -> 4 iters
        const uint32_t flat0 = (uint32_t)c * 32u;
        const uint32_t ij_s  = flat0 / KXP;
        const int      rem   = (int)(flat0 - ij_s * KXP);
        const uint32_t wbase = (uint32_t)(S2_WST + p * 4224);
#pragma unroll
        for (int it = 0; it < 4; it++) {
            int idx = it * 256 + tid;
            int row = idx >> 5;              // 0..31
            int q   = (idx & 31) * 4;        // fp32 col
            int loc = rem + row;
            int add = (loc >= KXP);
            int cc  = loc - (add ? KXP : 0);
            uint32_t ij = ij_s + (uint32_t)add;
            const float* src = (cc < KX && ij < NIJ)
                ? (W1 + ((size_t)ij * KX + cc) * PF + q) : g_zero;
            CPA16(smb + (wbase + (uint32_t)(row * WS2 + q)) * 4, src);
        }
        asm volatile("cp.async.commit_group;");
    };

    int c = blockIdx.x;
    stage(c, 0);
    int p = 0;

    while (c < NCHUNK) {
        const int cnext = c + NSPLIT;
        asm volatile("cp.async.wait_group 0;");
        __syncthreads();                       // data visible; prev compute done
        if (cnext < NCHUNK) stage(cnext, p ^ 1);

        // ---- convert Wstage[p] -> B planes (smem-local) ----
        {
            const float* wst = reinterpret_cast<const float*>(smw + S2_WST + p * 4224);
            uint32_t* Bhi = smw + S2_BHI;
            uint32_t* Blo = smw + S2_BLO;
#pragma unroll
            for (int it = 0; it < 8; it++) {
                int pidx = it * 256 + tid;     // 0..2047 pairs
                int row  = pidx >> 6;          // 0..31
                int pc   = pidx & 63;
                float2 w = *reinterpret_cast<const float2*>(&wst[row * WS2 + 2 * pc]);
                uint32_t h, l;
                cvt2(w.x, w.y, h, l);
                Bhi[row * XSTR + pc] = h;
                Blo[row * XSTR + pc] = l;
            }
        }
        __syncthreads();

        // ---- compute: 2 ksteps x 3 combos ----
        const uint32_t aAhi = smb + (uint32_t)(S2_ABUF + p * 5120) * 4 + aOff;
        const uint32_t aAlo = aAhi + 2560 * 4;
#pragma unroll
        for (int ks = 0; ks < 2; ks++) {
            uint32_t bh[8], bl[8];
            const uint32_t bk = (uint32_t)ks * 16 * (XSTR * 4);
            ldsm4t(bh + 0, aBhi + bk);
            ldsm4t(bh + 4, aBhi + bk + 32);
            ldsm4t(bl + 0, aBlo + bk);
            ldsm4t(bl + 4, aBlo + bk + 32);
#pragma unroll
            for (int mt = 0; mt < 4; mt++) {
                const uint32_t am = (uint32_t)mt * 16 * (PSTR2 * 4) + (uint32_t)ks * 32;
                uint32_t ah[4], al[4];
                ldsm4(ah, aAhi + am);
                ldsm4(al, aAlo + am);
#pragma unroll
                for (int nt = 0; nt < 4; nt++) {
                    mma_bf16(acc[mt][nt], ah, &bh[2 * nt]);
                    mma_bf16(acc[mt][nt], ah, &bl[2 * nt]);
                    mma_bf16(acc[mt][nt], al, &bh[2 * nt]);
                }
            }
        }
        p ^= 1;
        c = cnext;
    }

    float* part = &g_part[(size_t)blockIdx.x * (B_ * PF)];
#pragma unroll
    for (int mt = 0; mt < 4; mt++) {
        int row = mbase + mt * 16 + g;
#pragma unroll
        for (int nt = 0; nt < 4; nt++) {
            int col = nbase + nt * 8 + 2 * tg;
            *reinterpret_cast<float2*>(&part[(size_t)row * PF + col]) =
                make_float2(acc[mt][nt][0], acc[mt][nt][1]);
            *reinterpret_cast<float2*>(&part[(size_t)(row + 8) * PF + col]) =
                make_float2(acc[mt][nt][2], acc[mt][nt][3]);
        }
    }
}

// ===========================================================================
__global__ void k_finish(const float* __restrict__ b1, const float* __restrict__ W2,
                         const float* __restrict__ b2, const float* __restrict__ W3,
                         const float* __restrict__ b3, float* __restrict__ out) {
    __shared__ float h1s[PF];
    __shared__ float red[PF];
    const int b = blockIdx.x;
    const int q = threadIdx.x;

    float s0 = 0.f, s1 = 0.f, s2 = 0.f, s3 = 0.f;
    const size_t off = (size_t)b * PF + q;
#pragma unroll 4
    for (int c = 0; c < NSPLIT; c += 4) {
        s0 += g_part[(size_t)(c + 0) * (B_ * PF) + off];
        s1 += g_part[(size_t)(c + 1) * (B_ * PF) + off];
        s2 += g_part[(size_t)(c + 2) * (B_ * PF) + off];
        s3 += g_part[(size_t)(c + 3) * (B_ * PF) + off];
    }
    float h1 = (s0 + s1) + (s2 + s3) + b1[q];
    h1s[q] = fmaxf(h1, 0.f);
    __syncthreads();

    float a0 = b2[q], a1 = 0.f, a2 = 0.f, a3 = 0.f;
#pragma unroll 8
    for (int pq = 0; pq < PF; pq += 4) {
        a0 = fmaf(h1s[pq + 0], W2[(pq + 0) * PF + q], a0);
        a1 = fmaf(h1s[pq + 1], W2[(pq + 1) * PF + q], a1);
        a2 = fmaf(h1s[pq + 2], W2[(pq + 2) * PF + q], a2);
        a3 = fmaf(h1s[pq + 3], W2[(pq + 3) * PF + q], a3);
    }
    float h2 = fmaxf((a0 + a1) + (a2 + a3), 0.f);

    red[q] = h2 * W3[q];
    __syncthreads();
    for (int s = 64; s > 0; s >>= 1) {
        if (q < s) red[q] += red[q + s];
        __syncthreads();
    }
    if (q == 0) {
        float z = red[0] + b3[0];
        out[b] = 6.f / (1.f + expf(-z)) - 3.f;
    }
}

// ---------------------------------------------------------------------------
extern "C" void kernel_launch(void* const* d_in, const int* in_sizes, int n_in,
                              void* d_out, int out_size) {
    const float* audio = (const float*)d_in[0];
    const float* video = (const float*)d_in[1];
    const float* text  = (const float*)d_in[2];
    const float* W1    = (const float*)d_in[3];
    const float* b1    = (const float*)d_in[4];
    const float* W2    = (const float*)d_in[5];
    const float* b2    = (const float*)d_in[6];
    const float* W3    = (const float*)d_in[7];
    const float* b3    = (const float*)d_in[8];
    float* out = (float*)d_out;

    cudaFuncSetAttribute(k_build_F, cudaFuncAttributeMaxDynamicSharedMemorySize, S1_BYTES);
    cudaFuncSetAttribute(k_gemm_mma, cudaFuncAttributeMaxDynamicSharedMemorySize, S2_BYTES);

    k_build_F<<<dim3(2, 128), 256, S1_BYTES>>>(audio, video, text);
    k_gemm_mma<<<NSPLIT, 256, S2_BYTES>>>(W1);
    k_finish<<<128, 128>>>(b1, W2, b2, W3, b3, out);
}